// round 2
// baseline (speedup 1.0000x reference)
#include <cuda_runtime.h>
#include <math.h>

#define Bn   8
#define Cn   16
#define Fn   256
#define F2n  129
#define Tn   512
#define BTn  4096            // Bn*Tn
#define CINn 32
#define Hn   16
#define NGRP 4128            // 2C * F2
#define NROW (BTn*F2n)       // 528384
#define PI2  6.283185307179586f

// ---------------- scratch (device globals; no runtime allocation) ----------------
__device__ __align__(128) float  g_xt  [(size_t)Bn*Tn*Cn*Fn];      // x transposed: (b,t,c,f)
__device__ __align__(128) float  g_y   [(size_t)NROW*CINn];        // spectra (bt,k,ch) raw
__device__ __align__(128) float2 g_xf  [(size_t)BTn*Cn*F2n];       // X(f): (bt,c,k) complex
__device__ __align__(128) float  g_gx  [(size_t)NROW*128];         // gate preacts (row, dir*64+gate)
__device__ __align__(128) float  g_hcat[(size_t)NROW*2*Hn];        // LSTM out concat: (bt,k,32)
__device__ __align__(128) float  g_outt[(size_t)Bn*Tn*Cn*Fn];      // output transposed (b,t,c,f)
__device__ __align__(128) float2 g_part[(size_t)BTn*16];           // per-warp (sum,sumsq)
__device__ __align__(128) float2 g_stats[BTn];                     // (mean, rstd)

// ---------------- helpers ----------------
__device__ __forceinline__ float fsigmoid(float x) {
    return __fdividef(1.0f, 1.0f + __expf(-x));
}
__device__ __forceinline__ float ftanh_(float x) {
    float e = __expf(2.0f * x);
    return 1.0f - __fdividef(2.0f, e + 1.0f);
}
__device__ __forceinline__ unsigned long long pack2(float a, float b) {
    unsigned long long r; asm("mov.b64 %0, {%1,%2};" : "=l"(r) : "f"(a), "f"(b)); return r;
}
__device__ __forceinline__ void unpack2(unsigned long long v, float& a, float& b) {
    asm("mov.b64 {%0,%1}, %2;" : "=f"(a), "=f"(b) : "l"(v));
}
__device__ __forceinline__ unsigned long long fma2(unsigned long long a, unsigned long long b,
                                                   unsigned long long c) {
    unsigned long long d;
    asm("fma.rn.f32x2 %0, %1, %2, %3;" : "=l"(d) : "l"(a), "l"(b), "l"(c));
    return d;
}

// ---------------- K0: transpose x (B,C,F,T) -> (B,T,C,F) ----------------
__global__ void ktrans_in(const float* __restrict__ x) {
    __shared__ float tile[32][33];
    int bc = blockIdx.z;
    int f0 = blockIdx.x * 32, t0 = blockIdx.y * 32;
    int tx = threadIdx.x, ty = threadIdx.y;
    const float* src = x + (size_t)bc * Fn * Tn;
#pragma unroll
    for (int i = 0; i < 32; i += 8)
        tile[ty + i][tx] = src[(size_t)(f0 + ty + i) * Tn + t0 + tx];
    __syncthreads();
    int b = bc >> 4, c = bc & 15;
    float* dst = g_xt + (size_t)b * Tn * Cn * Fn + (size_t)c * Fn;
#pragma unroll
    for (int i = 0; i < 32; i += 8)
        dst[(size_t)(t0 + ty + i) * (Cn * Fn) + f0 + tx] = tile[tx][ty + i];
}

// ---------------- K1: forward rfft 256 -> 129 ----------------
// block = (bt, c-half); warp wi handles c = half*8+wi. Stage2 uses twiddle recurrence.
__global__ __launch_bounds__(256) void kfft_fwd() {
    __shared__ float2 tw[256];                // (cos,sin) 2pi j/256
    __shared__ float2 t16[256];               // [n1*16+m]: (cos,sin) 2pi n1 m/16
    __shared__ float  xs[8][256];
    __shared__ float2 As[8][256];
    __shared__ float  ytile[129 * 17];        // [k][16ch-half] padded
    int tid = threadIdx.x;
    {
        float s, c;
        sincosf((float)tid * (PI2 / 256.0f), &s, &c);
        tw[tid] = make_float2(c, s);
        int n1 = tid >> 4, m = tid & 15;
        sincosf((float)((n1 * m) & 15) * (PI2 / 16.0f), &s, &c);
        t16[tid] = make_float2(c, s);
    }
    __syncthreads();

    int wi = tid >> 5, l = tid & 31;
    int bh = blockIdx.x;
    int bt = bh >> 1, half = bh & 1;
    int c  = half * 8 + wi;

    const float* __restrict__ xrow = g_xt + ((size_t)bt * 16 + c) * 256;
#pragma unroll
    for (int q = 0; q < 8; q++) xs[wi][l + 32 * q] = xrow[l + 32 * q];
    __syncwarp();

    // stage 1: real-input 16-pt DFTs
    int m16 = l & 15;
    float c16[16], s16[16];
#pragma unroll
    for (int n1 = 0; n1 < 16; n1++) {
        float2 t = t16[n1 * 16 + m16];
        c16[n1] = t.x; s16[n1] = t.y;
    }
#pragma unroll
    for (int q = 0; q < 8; q++) {
        int p = l + 32 * q, n0 = p >> 4;
        float ar = 0.f, ai = 0.f;
#pragma unroll
        for (int n1 = 0; n1 < 16; n1++) {
            float v = xs[wi][n1 * 16 + n0];
            ar += v * c16[n1];
            ai -= v * s16[n1];
        }
        As[wi][p] = make_float2(ar, ai);
    }
    __syncwarp();

    // stage 2: recurrence twiddles (u = W^{n0}, W = e^{-2pi i k/256} via conj handling)
    float2 Av[16];
#pragma unroll
    for (int n0 = 0; n0 < 16; n0++) Av[n0] = As[wi][n0 * 16 + m16];

    float lsum = 0.f, lsq = 0.f;
#pragma unroll
    for (int q = 0; q < 5; q++) {
        int k = l + 32 * q;
        if (k < 129) {
            float2 W = tw[k];                  // (cos, sin) of 2pi k/256
            float ur = 1.f, ui = 0.f;
            float xr = Av[0].x, xi = Av[0].y;  // n0 = 0
#pragma unroll
            for (int n0 = 1; n0 < 16; n0++) {
                float nr = ur * W.x - ui * W.y;
                float ni = ur * W.y + ui * W.x;
                ur = nr; ui = ni;
                xr += ur * Av[n0].x + ui * Av[n0].y;   // Re(e^{-i}A)
                xi += ur * Av[n0].y - ui * Av[n0].x;   // Im(e^{-i}A)
            }
            ytile[k * 17 + wi]     = xr;
            ytile[k * 17 + 8 + wi] = xi;
            g_xf[((size_t)bt * 16 + c) * 129 + k] = make_float2(xr, xi);
            lsum += xr + xi;
            lsq  += xr * xr + xi * xi;
        }
    }
#pragma unroll
    for (int o = 16; o > 0; o >>= 1) {
        lsum += __shfl_down_sync(0xffffffffu, lsum, o);
        lsq  += __shfl_down_sync(0xffffffffu, lsq, o);
    }
    if (l == 0) g_part[(size_t)bt * 16 + c] = make_float2(lsum, lsq);

    __syncthreads();
    // cooperative sector-coalesced write of this half's 16 channels
    for (int e = tid; e < 129 * 16; e += 256) {
        int k = e >> 4, j = e & 15;
        int ch = (j < 8) ? (half * 8 + j) : (16 + half * 8 + (j - 8));
        g_y[((size_t)bt * 129 + k) * 32 + ch] = ytile[k * 17 + j];
    }
}

// ---------------- K2: deterministic stats reduce ----------------
__global__ void kstats() {
    int i = blockIdx.x * blockDim.x + threadIdx.x;
    if (i >= BTn) return;
    float s1 = 0.f, s2 = 0.f;
#pragma unroll
    for (int j = 0; j < 16; j++) {
        float2 p = g_part[(size_t)i * 16 + j];
        s1 += p.x; s2 += p.y;
    }
    float mean = s1 * (1.0f / NGRP);
    float var  = (s2 - s1 * s1 * (1.0f / NGRP)) * (1.0f / (NGRP - 1));
    float sd   = sqrtf(fmaxf(var, 0.f)) + 1e-8f;
    g_stats[i] = make_float2(mean, __fdividef(1.0f, sd));
}

// ---------------- K3: normalize + gate preactivations (both dirs) ----------------
#define GR 16
__global__ __launch_bounds__(128) void kgates(
    const float* __restrict__ nw, const float* __restrict__ nb,
    const float* __restrict__ wihf, const float* __restrict__ bihf, const float* __restrict__ bhhf,
    const float* __restrict__ wihb, const float* __restrict__ bihb, const float* __restrict__ bhhb) {
    __shared__ float ys[GR * 32];
    int tid = threadIdx.x;
    int dir = tid >> 6, gt = tid & 63;
    const float* wih = dir ? wihb : wihf;
    unsigned long long w2[16];
#pragma unroll
    for (int i = 0; i < 16; i++)
        w2[i] = pack2(wih[gt * 32 + 2 * i], wih[gt * 32 + 2 * i + 1]);
    float bias = dir ? (bihb[gt] + bhhb[gt]) : (bihf[gt] + bhhf[gt]);

    int row0 = blockIdx.x * GR;
    int ch = tid & 31;
#pragma unroll
    for (int j = 0; j < GR / 4; j++) {
        int rl = (tid >> 5) + 4 * j;
        int row = row0 + rl;
        int bt = row / 129;
        int k  = row - bt * 129;
        float2 st = g_stats[bt];
        float v = g_y[(size_t)row * 32 + ch];
        ys[rl * 32 + ch] = (v - st.x) * st.y * nw[ch * 129 + k] + nb[ch * 129 + k];
    }
    __syncthreads();

#pragma unroll
    for (int r = 0; r < GR; r++) {
        const ulonglong2* yp = reinterpret_cast<const ulonglong2*>(&ys[r * 32]);
        unsigned long long acc2 = pack2(bias, 0.f);
#pragma unroll
        for (int i = 0; i < 8; i++) {
            ulonglong2 y2 = yp[i];
            acc2 = fma2(w2[2 * i],     y2.x, acc2);
            acc2 = fma2(w2[2 * i + 1], y2.y, acc2);
        }
        float aa, ab; unpack2(acc2, aa, ab);
        g_gx[(size_t)(row0 + r) * 128 + tid] = aa + ab;
    }
}

// ---------------- K4: recurrent LSTM (gates precomputed) ----------------
__global__ void __launch_bounds__(256) klstm(
    const float* __restrict__ whhf, const float* __restrict__ whhb) {
    int tid = threadIdx.x, wi = tid >> 5, l = tid & 31;
    int g = blockIdx.x * 8 + wi;
    int s = g >> 1, dir = g & 1;
    const float* whh = dir ? whhb : whhf;

    float wh0[16], wh1[16];
#pragma unroll
    for (int q = 0; q < 16; q++) { wh0[q] = whh[l * 16 + q]; wh1[q] = whh[(l + 32) * 16 + q]; }

    float hv[16];
#pragma unroll
    for (int q = 0; q < 16; q++) hv[q] = 0.f;
    float cst = 0.f;

    const float* __restrict__ base = g_gx + (size_t)s * 129 * 128 + (dir << 6);
    float* __restrict__ hout = g_hcat + (size_t)s * 129 * 32 + (dir << 4);

    int f = dir ? 128 : 0;
    int stp = dir ? -1 : 1;
    float a0 = base[f * 128 + l];
    float a1 = base[f * 128 + 32 + l];

    for (int step = 0; step < 129; step++) {
        float b0 = 0.f, b1 = 0.f;
        int fn = f + stp;
        if (step < 128) {
            b0 = base[fn * 128 + l];
            b1 = base[fn * 128 + 32 + l];
        }
        float ac0 = a0, ac0b = 0.f, ac1 = a1, ac1b = 0.f;
#pragma unroll
        for (int q = 0; q < 16; q += 2) {
            ac0  += wh0[q] * hv[q];      ac0b += wh0[q + 1] * hv[q + 1];
            ac1  += wh1[q] * hv[q];      ac1b += wh1[q + 1] * hv[q + 1];
        }
        float acc0 = ac0 + ac0b, acc1 = ac1 + ac1b;
        float g0 = fsigmoid(acc0);                        // i / f
        float g1 = (l < 16) ? ftanh_(acc1) : fsigmoid(acc1);  // g / o
        float fg = __shfl_sync(0xffffffffu, g0, (l + 16) & 31);
        float og = __shfl_sync(0xffffffffu, g1, (l + 16) & 31);
        float cn = fg * cst + g0 * g1;
        float hn = og * ftanh_(cn);
        cst = cn;
        if (l < 16) hout[f * 32 + l] = hn;
#pragma unroll
        for (int q = 0; q < 16; q++) hv[q] = __shfl_sync(0xffffffffu, hn, q);
        a0 = b0; a1 = b1; f = fn;
    }
}

// ---------------- K5: linear + spectrum multiply + irfft ----------------
__global__ __launch_bounds__(256) void kinv(const float* __restrict__ lin_w,
                                            const float* __restrict__ lin_b) {
    __shared__ float2 tw[256];
    __shared__ float2 t16[256];
    __shared__ float2 Ss[8][256];
    __shared__ float2 Bs[8][256];
    int tid = threadIdx.x;
    {
        float s, c;
        sincosf((float)tid * (PI2 / 256.0f), &s, &c);
        tw[tid] = make_float2(c, s);
        int n1 = tid >> 4, m = tid & 15;
        sincosf((float)((n1 * m) & 15) * (PI2 / 16.0f), &s, &c);
        t16[tid] = make_float2(c, s);
    }
    __syncthreads();

    int wi = tid >> 5, l = tid & 31;
    int g  = blockIdx.x * 8 + wi;
    int bt = g >> 4, c = g & 15;

    unsigned long long w0p[16], w1p[16];
#pragma unroll
    for (int i = 0; i < 16; i++) {
        w0p[i] = pack2(lin_w[c * 32 + 2 * i],        lin_w[c * 32 + 2 * i + 1]);
        w1p[i] = pack2(lin_w[(c + 16) * 32 + 2 * i], lin_w[(c + 16) * 32 + 2 * i + 1]);
    }
    float lb0 = lin_b[c], lb1 = lin_b[c + 16];

    // linear + complex multiply, fill hermitian spectrum
#pragma unroll
    for (int q = 0; q < 5; q++) {
        int k = l + 32 * q;
        if (k < 129) {
            const ulonglong2* hp =
                reinterpret_cast<const ulonglong2*>(g_hcat + ((size_t)bt * 129 + k) * 32);
            unsigned long long re2 = pack2(lb0, 0.f);
            unsigned long long im2 = pack2(lb1, 0.f);
#pragma unroll
            for (int j = 0; j < 8; j++) {
                ulonglong2 h2 = hp[j];
                re2 = fma2(w0p[2 * j],     h2.x, re2);
                re2 = fma2(w0p[2 * j + 1], h2.y, re2);
                im2 = fma2(w1p[2 * j],     h2.x, im2);
                im2 = fma2(w1p[2 * j + 1], h2.y, im2);
            }
            float ra, rb, ia, ib;
            unpack2(re2, ra, rb); unpack2(im2, ia, ib);
            float re = ra + rb, im = ia + ib;
            float2 xf = g_xf[((size_t)bt * 16 + c) * 129 + k];
            float pr = re * xf.x - im * xf.y;
            float pi = re * xf.y + im * xf.x;
            Ss[wi][k] = make_float2(pr, pi);
            if (k >= 1 && k <= 127) Ss[wi][256 - k] = make_float2(pr, -pi);
        }
    }
    __syncwarp();

    // inverse stage 1
    int m16 = l & 15;
    float c16[16], s16[16];
#pragma unroll
    for (int k1 = 0; k1 < 16; k1++) {
        float2 t = t16[k1 * 16 + m16];
        c16[k1] = t.x; s16[k1] = t.y;
    }
#pragma unroll
    for (int q = 0; q < 8; q++) {
        int p = l + 32 * q, k0 = p >> 4;
        float br = 0.f, bi = 0.f;
#pragma unroll
        for (int k1 = 0; k1 < 16; k1++) {
            float2 v = Ss[wi][k1 * 16 + k0];
            br += v.x * c16[k1] - v.y * s16[k1];
            bi += v.x * s16[k1] + v.y * c16[k1];
        }
        Bs[wi][p] = make_float2(br, bi);
    }
    __syncwarp();

    // inverse stage 2 (real output) with recurrence twiddles
    float2 Bv[16];
#pragma unroll
    for (int k0 = 0; k0 < 16; k0++) Bv[k0] = Bs[wi][k0 * 16 + m16];
    float* orow = g_outt + (size_t)g * 256;
#pragma unroll
    for (int q = 0; q < 8; q++) {
        int n = l + 32 * q;
        float2 V = tw[n];                      // e^{+2pi i n/256}
        float ur = 1.f, ui = 0.f;
        float acc = Bv[0].x;
#pragma unroll
        for (int k0 = 1; k0 < 16; k0++) {
            float nr = ur * V.x - ui * V.y;
            float ni = ur * V.y + ui * V.x;
            ur = nr; ui = ni;
            acc += Bv[k0].x * ur - Bv[k0].y * ui;
        }
        orow[n] = acc * (1.0f / 256.0f);
    }
}

// ---------------- K6: transpose (B,T,C,F) -> (B,C,F,T) ----------------
__global__ void ktrans_out(float* __restrict__ out) {
    __shared__ float tile[32][33];
    int bc = blockIdx.z;
    int b = bc >> 4, c = bc & 15;
    int f0 = blockIdx.x * 32, t0 = blockIdx.y * 32;
    int tx = threadIdx.x, ty = threadIdx.y;
    const float* src = g_outt + (size_t)b * Tn * Cn * Fn + (size_t)c * Fn;
#pragma unroll
    for (int i = 0; i < 32; i += 8)
        tile[ty + i][tx] = src[(size_t)(t0 + ty + i) * (Cn * Fn) + f0 + tx];
    __syncthreads();
    float* dst = out + (size_t)bc * Fn * Tn;
#pragma unroll
    for (int i = 0; i < 32; i += 8)
        dst[(size_t)(f0 + ty + i) * Tn + t0 + tx] = tile[tx][ty + i];
}

// ---------------- launch ----------------
extern "C" void kernel_launch(void* const* d_in, const int* in_sizes, int n_in,
                              void* d_out, int out_size) {
    const float* x      = (const float*)d_in[0];
    const float* norm_w = (const float*)d_in[1];
    const float* norm_b = (const float*)d_in[2];
    const float* w_ih_f = (const float*)d_in[3];
    const float* w_hh_f = (const float*)d_in[4];
    const float* b_ih_f = (const float*)d_in[5];
    const float* b_hh_f = (const float*)d_in[6];
    const float* w_ih_b = (const float*)d_in[7];
    const float* w_hh_b = (const float*)d_in[8];
    const float* b_ih_b = (const float*)d_in[9];
    const float* b_hh_b = (const float*)d_in[10];
    const float* lin_w  = (const float*)d_in[11];
    const float* lin_b  = (const float*)d_in[12];
    float* out = (float*)d_out;

    dim3 tgrid(Fn / 32, Tn / 32, Bn * Cn);
    dim3 tblk(32, 8);

    ktrans_in<<<tgrid, tblk>>>(x);
    kfft_fwd<<<BTn * 2, 256>>>();
    kstats<<<(BTn + 255) / 256, 256>>>();
    kgates<<<NROW / GR, 128>>>(norm_w, norm_b,
                               w_ih_f, b_ih_f, b_hh_f,
                               w_ih_b, b_ih_b, b_hh_b);
    klstm<<<(BTn * 2) / 8, 256>>>(w_hh_f, w_hh_b);
    kinv<<<(BTn * 16) / 8, 256>>>(lin_w, lin_b);
    ktrans_out<<<tgrid, tblk>>>(out);
}

// round 3
// speedup vs baseline: 1.6298x; 1.6298x over previous
#include <cuda_runtime.h>
#include <math.h>

#define Bn   8
#define Cn   16
#define Fn   256
#define F2n  129
#define Tn   512
#define BTn  4096            // Bn*Tn
#define CINn 32
#define Hn   16
#define NGRP 4128            // 2C * F2
#define NROW (BTn*F2n)       // 528384
#define PI2  6.283185307179586f

// ---------------- scratch (device globals; no runtime allocation) ----------------
__device__ __align__(128) float  g_xt  [(size_t)Bn*Tn*Cn*Fn];      // x transposed: (b,t,c,f)
__device__ __align__(128) float  g_y   [(size_t)NROW*CINn];        // spectra (bt,k,ch) raw
__device__ __align__(128) float2 g_xf  [(size_t)BTn*Cn*F2n];       // X(f): (bt,c,k) complex
__device__ __align__(128) float  g_gx  [(size_t)NROW*128];         // gate preacts (row, dir*64+gate)
__device__ __align__(128) float  g_hcat[(size_t)NROW*2*Hn];        // LSTM out concat: (bt,k,32)
__device__ __align__(128) float  g_outt[(size_t)Bn*Tn*Cn*Fn];      // output transposed (b,t,c,f)
__device__ __align__(128) float2 g_part[(size_t)BTn*16];           // per-warp (sum,sumsq)
__device__ __align__(128) float2 g_stats[BTn];                     // (mean, rstd)
// prepped params
__device__ __align__(16)  float  g_nwt[F2n*32];                    // nw transposed [k][ch]
__device__ __align__(16)  float  g_nbt[F2n*32];
__device__ __align__(16)  float4 g_wc4[8*128];                     // W combined [c4][gate] (4 ch each)
__device__ __align__(16)  float  g_bc [128];                       // combined bias per gate

// ---------------- helpers ----------------
__device__ __forceinline__ float fsigmoid(float x) {
    return __fdividef(1.0f, 1.0f + __expf(-x));
}
__device__ __forceinline__ float ftanh_(float x) {
    float e = __expf(2.0f * x);
    return 1.0f - __fdividef(2.0f, e + 1.0f);
}
__device__ __forceinline__ unsigned long long pack2(float a, float b) {
    unsigned long long r; asm("mov.b64 %0, {%1,%2};" : "=l"(r) : "f"(a), "f"(b)); return r;
}
__device__ __forceinline__ void unpack2(unsigned long long v, float& a, float& b) {
    asm("mov.b64 {%0,%1}, %2;" : "=f"(a), "=f"(b) : "l"(v));
}
__device__ __forceinline__ unsigned long long fma2(unsigned long long a, unsigned long long b,
                                                   unsigned long long c) {
    unsigned long long d;
    asm("fma.rn.f32x2 %0, %1, %2, %3;" : "=l"(d) : "l"(a), "l"(b), "l"(c));
    return d;
}

// ---------------- K-1: pre-pack params ----------------
__global__ void kprep(const float* __restrict__ nw, const float* __restrict__ nb,
                      const float* __restrict__ wihf, const float* __restrict__ bihf,
                      const float* __restrict__ bhhf,
                      const float* __restrict__ wihb, const float* __restrict__ bihb,
                      const float* __restrict__ bhhb) {
    int i = blockIdx.x * blockDim.x + threadIdx.x;
    if (i < NGRP) {                                   // transpose norm params
        int ch = i / F2n, k = i - ch * F2n;
        g_nwt[k * 32 + ch] = nw[i];
        g_nbt[k * 32 + ch] = nb[i];
    } else if (i < NGRP + 4096) {                     // combined gate weights
        int j = i - NGRP;
        int g = j >> 5, ch = j & 31;
        float v = (g < 64) ? wihf[g * 32 + ch] : wihb[(g - 64) * 32 + ch];
        reinterpret_cast<float*>(g_wc4)[(ch >> 2) * 512 + g * 4 + (ch & 3)] = v;
    } else if (i < NGRP + 4096 + 128) {               // combined bias
        int g = i - NGRP - 4096;
        g_bc[g] = (g < 64) ? (bihf[g] + bhhf[g]) : (bihb[g - 64] + bhhb[g - 64]);
    }
}

// ---------------- K0: transpose x (B,C,F,T) -> (B,T,C,F) ----------------
__global__ void ktrans_in(const float* __restrict__ x) {
    __shared__ float tile[32][33];
    int bc = blockIdx.z;
    int f0 = blockIdx.x * 32, t0 = blockIdx.y * 32;
    int tx = threadIdx.x, ty = threadIdx.y;
    const float* src = x + (size_t)bc * Fn * Tn;
#pragma unroll
    for (int i = 0; i < 32; i += 8)
        tile[ty + i][tx] = src[(size_t)(f0 + ty + i) * Tn + t0 + tx];
    __syncthreads();
    int b = bc >> 4, c = bc & 15;
    float* dst = g_xt + (size_t)b * Tn * Cn * Fn + (size_t)c * Fn;
#pragma unroll
    for (int i = 0; i < 32; i += 8)
        dst[(size_t)(t0 + ty + i) * (Cn * Fn) + f0 + tx] = tile[tx][ty + i];
}

// ---------------- K1: forward rfft 256 -> 129 ----------------
__global__ __launch_bounds__(256) void kfft_fwd() {
    __shared__ float2 tw[256];
    __shared__ float2 t16[256];
    __shared__ float  xs[8][256];
    __shared__ float2 As[8][256];
    __shared__ float  ytile[129 * 17];
    int tid = threadIdx.x;
    {
        float s, c;
        sincosf((float)tid * (PI2 / 256.0f), &s, &c);
        tw[tid] = make_float2(c, s);
        int n1 = tid >> 4, m = tid & 15;
        sincosf((float)((n1 * m) & 15) * (PI2 / 16.0f), &s, &c);
        t16[tid] = make_float2(c, s);
    }
    __syncthreads();

    int wi = tid >> 5, l = tid & 31;
    int bh = blockIdx.x;
    int bt = bh >> 1, half = bh & 1;
    int c  = half * 8 + wi;

    const float* __restrict__ xrow = g_xt + ((size_t)bt * 16 + c) * 256;
#pragma unroll
    for (int q = 0; q < 8; q++) xs[wi][l + 32 * q] = xrow[l + 32 * q];
    __syncwarp();

    int m16 = l & 15;
    float c16[16], s16[16];
#pragma unroll
    for (int n1 = 0; n1 < 16; n1++) {
        float2 t = t16[n1 * 16 + m16];
        c16[n1] = t.x; s16[n1] = t.y;
    }
#pragma unroll
    for (int q = 0; q < 8; q++) {
        int p = l + 32 * q, n0 = p >> 4;
        float ar = 0.f, ai = 0.f;
#pragma unroll
        for (int n1 = 0; n1 < 16; n1++) {
            float v = xs[wi][n1 * 16 + n0];
            ar += v * c16[n1];
            ai -= v * s16[n1];
        }
        As[wi][p] = make_float2(ar, ai);
    }
    __syncwarp();

    float2 Av[16];
#pragma unroll
    for (int n0 = 0; n0 < 16; n0++) Av[n0] = As[wi][n0 * 16 + m16];

    float lsum = 0.f, lsq = 0.f;
#pragma unroll
    for (int q = 0; q < 5; q++) {
        int k = l + 32 * q;
        if (k < 129) {
            float2 W = tw[k];
            float ur = 1.f, ui = 0.f;
            float xr = Av[0].x, xi = Av[0].y;
#pragma unroll
            for (int n0 = 1; n0 < 16; n0++) {
                float nr = ur * W.x - ui * W.y;
                float ni = ur * W.y + ui * W.x;
                ur = nr; ui = ni;
                xr += ur * Av[n0].x + ui * Av[n0].y;
                xi += ur * Av[n0].y - ui * Av[n0].x;
            }
            ytile[k * 17 + wi]     = xr;
            ytile[k * 17 + 8 + wi] = xi;
            g_xf[((size_t)bt * 16 + c) * 129 + k] = make_float2(xr, xi);
            lsum += xr + xi;
            lsq  += xr * xr + xi * xi;
        }
    }
#pragma unroll
    for (int o = 16; o > 0; o >>= 1) {
        lsum += __shfl_down_sync(0xffffffffu, lsum, o);
        lsq  += __shfl_down_sync(0xffffffffu, lsq, o);
    }
    if (l == 0) g_part[(size_t)bt * 16 + c] = make_float2(lsum, lsq);

    __syncthreads();
    for (int e = tid; e < 129 * 16; e += 256) {
        int k = e >> 4, j = e & 15;
        int ch = (j < 8) ? (half * 8 + j) : (16 + half * 8 + (j - 8));
        g_y[((size_t)bt * 129 + k) * 32 + ch] = ytile[k * 17 + j];
    }
}

// ---------------- K2: deterministic stats reduce ----------------
__global__ void kstats() {
    int i = blockIdx.x * blockDim.x + threadIdx.x;
    if (i >= BTn) return;
    float s1 = 0.f, s2 = 0.f;
#pragma unroll
    for (int j = 0; j < 16; j++) {
        float2 p = g_part[(size_t)i * 16 + j];
        s1 += p.x; s2 += p.y;
    }
    float mean = s1 * (1.0f / NGRP);
    float var  = (s2 - s1 * s1 * (1.0f / NGRP)) * (1.0f / (NGRP - 1));
    float sd   = sqrtf(fmaxf(var, 0.f)) + 1e-8f;
    g_stats[i] = make_float2(mean, __fdividef(1.0f, sd));
}

// ---------------- K3: normalize + gate GEMM (register-blocked) ----------------
// block: 64 rows x 128 gates; thread: 8 gates (stride 16) x 4 rows, f32x2 k-packing
#define ROWS_B 64
__global__ __launch_bounds__(256, 2) void kgates() {
    __shared__ float4 ws4[8 * 128];        // [c4][gate]
    __shared__ float4 ys4[8 * 65];         // [c4][row] padded 64->65

    int tid = threadIdx.x;
    int row0 = blockIdx.x * ROWS_B;

    // load + normalize y tile into k-major float4 slots
#pragma unroll
    for (int j = 0; j < 8; j++) {
        int e = tid + 256 * j;             // 2048 elems
        int rloc = e >> 5, ch = e & 31;
        int row = row0 + rloc;
        int bt = row / 129;
        int k  = row - bt * 129;
        float2 st = g_stats[bt];
        float v = g_y[(size_t)row * 32 + ch];
        float nv = (v - st.x) * st.y * g_nwt[k * 32 + ch] + g_nbt[k * 32 + ch];
        reinterpret_cast<float*>(ys4)[(ch >> 2) * 260 + rloc * 4 + (ch & 3)] = nv;
    }
    // copy W tile
#pragma unroll
    for (int j = 0; j < 4; j++) ws4[tid + 256 * j] = g_wc4[tid + 256 * j];
    __syncthreads();

    int gl = tid & 15;                     // gate base (stride 16)
    int r0 = (tid >> 4) * 4;               // 4 rows

    unsigned long long acc[8][4];
#pragma unroll
    for (int gi = 0; gi < 8; gi++)
#pragma unroll
        for (int r = 0; r < 4; r++) acc[gi][r] = 0ull;

#pragma unroll
    for (int c4 = 0; c4 < 8; c4++) {
        ulonglong2 yv[4];
#pragma unroll
        for (int r = 0; r < 4; r++)
            yv[r] = *reinterpret_cast<const ulonglong2*>(&ys4[c4 * 65 + r0 + r]);
#pragma unroll
        for (int gi = 0; gi < 8; gi++) {
            ulonglong2 wv = *reinterpret_cast<const ulonglong2*>(&ws4[c4 * 128 + gl + 16 * gi]);
#pragma unroll
            for (int r = 0; r < 4; r++) {
                acc[gi][r] = fma2(wv.x, yv[r].x, acc[gi][r]);
                acc[gi][r] = fma2(wv.y, yv[r].y, acc[gi][r]);
            }
        }
    }

#pragma unroll
    for (int gi = 0; gi < 8; gi++) {
        int g = gl + 16 * gi;
        float bias = g_bc[g];
#pragma unroll
        for (int r = 0; r < 4; r++) {
            float a, b; unpack2(acc[gi][r], a, b);
            g_gx[(size_t)(row0 + r0 + r) * 128 + g] = a + b + bias;
        }
    }
}

// ---------------- K4: recurrent LSTM (gates precomputed) ----------------
__global__ void __launch_bounds__(256) klstm(
    const float* __restrict__ whhf, const float* __restrict__ whhb) {
    int tid = threadIdx.x, wi = tid >> 5, l = tid & 31;
    int g = blockIdx.x * 8 + wi;
    int s = g >> 1, dir = g & 1;
    const float* whh = dir ? whhb : whhf;

    float wh0[16], wh1[16];
#pragma unroll
    for (int q = 0; q < 16; q++) { wh0[q] = whh[l * 16 + q]; wh1[q] = whh[(l + 32) * 16 + q]; }

    float hv[16];
#pragma unroll
    for (int q = 0; q < 16; q++) hv[q] = 0.f;
    float cst = 0.f;

    const float* __restrict__ base = g_gx + (size_t)s * 129 * 128 + (dir << 6);
    float* __restrict__ hout = g_hcat + (size_t)s * 129 * 32 + (dir << 4);

    int f = dir ? 128 : 0;
    int stp = dir ? -1 : 1;
    float a0 = base[f * 128 + l];
    float a1 = base[f * 128 + 32 + l];

    for (int step = 0; step < 129; step++) {
        float b0 = 0.f, b1 = 0.f;
        int fn = f + stp;
        if (step < 128) {
            b0 = base[fn * 128 + l];
            b1 = base[fn * 128 + 32 + l];
        }
        float ac0 = a0, ac0b = 0.f, ac1 = a1, ac1b = 0.f;
#pragma unroll
        for (int q = 0; q < 16; q += 2) {
            ac0  += wh0[q] * hv[q];      ac0b += wh0[q + 1] * hv[q + 1];
            ac1  += wh1[q] * hv[q];      ac1b += wh1[q + 1] * hv[q + 1];
        }
        float acc0 = ac0 + ac0b, acc1 = ac1 + ac1b;
        float g0 = fsigmoid(acc0);
        float g1 = (l < 16) ? ftanh_(acc1) : fsigmoid(acc1);
        float fg = __shfl_sync(0xffffffffu, g0, (l + 16) & 31);
        float og = __shfl_sync(0xffffffffu, g1, (l + 16) & 31);
        float cn = fg * cst + g0 * g1;
        float hn = og * ftanh_(cn);
        cst = cn;
        if (l < 16) hout[f * 32 + l] = hn;
#pragma unroll
        for (int q = 0; q < 16; q++) hv[q] = __shfl_sync(0xffffffffu, hn, q);
        a0 = b0; a1 = b1; f = fn;
    }
}

// ---------------- K5: linear + spectrum multiply + irfft ----------------
__global__ __launch_bounds__(256) void kinv(const float* __restrict__ lin_w,
                                            const float* __restrict__ lin_b) {
    __shared__ float2 tw[256];
    __shared__ float2 t16[256];
    __shared__ float2 Ss[8][256];
    __shared__ float2 Bs[8][256];
    int tid = threadIdx.x;
    {
        float s, c;
        sincosf((float)tid * (PI2 / 256.0f), &s, &c);
        tw[tid] = make_float2(c, s);
        int n1 = tid >> 4, m = tid & 15;
        sincosf((float)((n1 * m) & 15) * (PI2 / 16.0f), &s, &c);
        t16[tid] = make_float2(c, s);
    }
    __syncthreads();

    int wi = tid >> 5, l = tid & 31;
    int g  = blockIdx.x * 8 + wi;
    int bt = g >> 4, c = g & 15;

    unsigned long long w0p[16], w1p[16];
#pragma unroll
    for (int i = 0; i < 16; i++) {
        w0p[i] = pack2(lin_w[c * 32 + 2 * i],        lin_w[c * 32 + 2 * i + 1]);
        w1p[i] = pack2(lin_w[(c + 16) * 32 + 2 * i], lin_w[(c + 16) * 32 + 2 * i + 1]);
    }
    float lb0 = lin_b[c], lb1 = lin_b[c + 16];

#pragma unroll
    for (int q = 0; q < 5; q++) {
        int k = l + 32 * q;
        if (k < 129) {
            const ulonglong2* hp =
                reinterpret_cast<const ulonglong2*>(g_hcat + ((size_t)bt * 129 + k) * 32);
            unsigned long long re2 = pack2(lb0, 0.f);
            unsigned long long im2 = pack2(lb1, 0.f);
#pragma unroll
            for (int j = 0; j < 8; j++) {
                ulonglong2 h2 = hp[j];
                re2 = fma2(w0p[2 * j],     h2.x, re2);
                re2 = fma2(w0p[2 * j + 1], h2.y, re2);
                im2 = fma2(w1p[2 * j],     h2.x, im2);
                im2 = fma2(w1p[2 * j + 1], h2.y, im2);
            }
            float ra, rb, ia, ib;
            unpack2(re2, ra, rb); unpack2(im2, ia, ib);
            float re = ra + rb, im = ia + ib;
            float2 xf = g_xf[((size_t)bt * 16 + c) * 129 + k];
            float pr = re * xf.x - im * xf.y;
            float pi = re * xf.y + im * xf.x;
            Ss[wi][k] = make_float2(pr, pi);
            if (k >= 1 && k <= 127) Ss[wi][256 - k] = make_float2(pr, -pi);
        }
    }
    __syncwarp();

    int m16 = l & 15;
    float c16[16], s16[16];
#pragma unroll
    for (int k1 = 0; k1 < 16; k1++) {
        float2 t = t16[k1 * 16 + m16];
        c16[k1] = t.x; s16[k1] = t.y;
    }
#pragma unroll
    for (int q = 0; q < 8; q++) {
        int p = l + 32 * q, k0 = p >> 4;
        float br = 0.f, bi = 0.f;
#pragma unroll
        for (int k1 = 0; k1 < 16; k1++) {
            float2 v = Ss[wi][k1 * 16 + k0];
            br += v.x * c16[k1] - v.y * s16[k1];
            bi += v.x * s16[k1] + v.y * c16[k1];
        }
        Bs[wi][p] = make_float2(br, bi);
    }
    __syncwarp();

    float2 Bv[16];
#pragma unroll
    for (int k0 = 0; k0 < 16; k0++) Bv[k0] = Bs[wi][k0 * 16 + m16];
    float* orow = g_outt + (size_t)g * 256;
#pragma unroll
    for (int q = 0; q < 8; q++) {
        int n = l + 32 * q;
        float2 V = tw[n];
        float ur = 1.f, ui = 0.f;
        float acc = Bv[0].x;
#pragma unroll
        for (int k0 = 1; k0 < 16; k0++) {
            float nr = ur * V.x - ui * V.y;
            float ni = ur * V.y + ui * V.x;
            ur = nr; ui = ni;
            acc += Bv[k0].x * ur - Bv[k0].y * ui;
        }
        orow[n] = acc * (1.0f / 256.0f);
    }
}

// ---------------- K6: transpose (B,T,C,F) -> (B,C,F,T) ----------------
__global__ void ktrans_out(float* __restrict__ out) {
    __shared__ float tile[32][33];
    int bc = blockIdx.z;
    int b = bc >> 4, c = bc & 15;
    int f0 = blockIdx.x * 32, t0 = blockIdx.y * 32;
    int tx = threadIdx.x, ty = threadIdx.y;
    const float* src = g_outt + (size_t)b * Tn * Cn * Fn + (size_t)c * Fn;
#pragma unroll
    for (int i = 0; i < 32; i += 8)
        tile[ty + i][tx] = src[(size_t)(t0 + ty + i) * (Cn * Fn) + f0 + tx];
    __syncthreads();
    float* dst = out + (size_t)bc * Fn * Tn;
#pragma unroll
    for (int i = 0; i < 32; i += 8)
        dst[(size_t)(f0 + ty + i) * Tn + t0 + tx] = tile[tx][ty + i];
}

// ---------------- launch ----------------
extern "C" void kernel_launch(void* const* d_in, const int* in_sizes, int n_in,
                              void* d_out, int out_size) {
    const float* x      = (const float*)d_in[0];
    const float* norm_w = (const float*)d_in[1];
    const float* norm_b = (const float*)d_in[2];
    const float* w_ih_f = (const float*)d_in[3];
    const float* w_hh_f = (const float*)d_in[4];
    const float* b_ih_f = (const float*)d_in[5];
    const float* b_hh_f = (const float*)d_in[6];
    const float* w_ih_b = (const float*)d_in[7];
    const float* w_hh_b = (const float*)d_in[8];
    const float* b_ih_b = (const float*)d_in[9];
    const float* b_hh_b = (const float*)d_in[10];
    const float* lin_w  = (const float*)d_in[11];
    const float* lin_b  = (const float*)d_in[12];
    float* out = (float*)d_out;

    dim3 tgrid(Fn / 32, Tn / 32, Bn * Cn);
    dim3 tblk(32, 8);

    kprep<<<(NGRP + 4096 + 128 + 255) / 256, 256>>>(norm_w, norm_b,
                                                    w_ih_f, b_ih_f, b_hh_f,
                                                    w_ih_b, b_ih_b, b_hh_b);
    ktrans_in<<<tgrid, tblk>>>(x);
    kfft_fwd<<<BTn * 2, 256>>>();
    kstats<<<(BTn + 255) / 256, 256>>>();
    kgates<<<NROW / ROWS_B, 256>>>();
    klstm<<<(BTn * 2) / 8, 256>>>(w_hh_f, w_hh_b);
    kinv<<<(BTn * 16) / 8, 256>>>(lin_w, lin_b);
    ktrans_out<<<tgrid, tblk>>>(out);
}